// round 4
// baseline (speedup 1.0000x reference)
#include <cuda_runtime.h>

#define NG      1024
#define IMG_W   256
#define IMG_H   256
#define TILE_SZ 64
#define FOCALF  256.0f
#define LOG2E   1.4426950408889634f

#define BLK_W   16
#define BLK_H   16
#define PAD     2.0f
#define NBLK    ((IMG_W / BLK_W) * (IMG_H / BLK_H))   // 16 x 16 = 256

// ---------------- device scratch ----------------
__device__ float4 g_A[NG];      // (mx, my, k*log2e, opacity)
__device__ float4 g_B[NG];      // (r, g, b, depth)
__device__ float4 g_R[NG];      // clamped rect (minx, miny, maxx, maxy)
__device__ unsigned long long g_key[NG];

// ---------------- 1) project all gaussians once ----------------
__global__ void k_project(const float* __restrict__ means3d,
                          const float* __restrict__ opacity,
                          const float* __restrict__ scale3d,
                          const float* __restrict__ features,
                          const float* __restrict__ V,
                          const float* __restrict__ P) {
    int g = blockIdx.x * blockDim.x + threadIdx.x;
    if (g >= NG) return;
    float x = means3d[3*g+0], y = means3d[3*g+1], z = means3d[3*g+2];

    float pv0 = x*V[0] + y*V[4] + z*V[8]  + V[12];
    float pv1 = x*V[1] + y*V[5] + z*V[9]  + V[13];
    float pv2 = x*V[2] + y*V[6] + z*V[10] + V[14];
    float pv3 = x*V[3] + y*V[7] + z*V[11] + V[15];

    float ph0 = pv0*P[0] + pv1*P[4] + pv2*P[8]  + pv3*P[12];
    float ph1 = pv0*P[1] + pv1*P[5] + pv2*P[9]  + pv3*P[13];
    float ph3 = pv0*P[3] + pv1*P[7] + pv2*P[11] + pv3*P[15];

    float invw = __fdividef(1.0f, ph3 + 1e-6f);
    float mx = ((ph0*invw + 1.0f) * (float)IMG_W - 1.0f) * 0.5f;
    float my = ((ph1*invw + 1.0f) * (float)IMG_H - 1.0f) * 0.5f;

    float tz    = pv2;
    float s2    = scale3d[g] * FOCALF * __fdividef(1.0f, tz);
    float radii = s2 * 5.0f;
    float k2    = __fdividef(-0.5f * LOG2E, s2 * s2);

    float rminx = fminf(fmaxf(mx - radii, 0.0f), (float)IMG_W - 1.0f);
    float rminy = fminf(fmaxf(my - radii, 0.0f), (float)IMG_H - 1.0f);
    float rmaxx = fminf(fmaxf(mx + radii, 0.0f), (float)IMG_W - 1.0f);
    float rmaxy = fminf(fmaxf(my + radii, 0.0f), (float)IMG_H - 1.0f);

    g_A[g] = make_float4(mx, my, k2, opacity[g]);
    g_B[g] = make_float4(features[3*g+0], features[3*g+1], features[3*g+2], tz);
    g_R[g] = make_float4(rminx, rminy, rmaxx, rmaxy);

    unsigned ku = __float_as_uint(tz);
    ku = (ku & 0x80000000u) ? ~ku : (ku | 0x80000000u);
    g_key[g] = ((unsigned long long)ku << 32) | (unsigned)g;   // unique, stable
}

// ---------------- 2) cull + sort + composite: 256 blocks, 16x16 px ----------------
__global__ void __launch_bounds__(256) k_render(float* __restrict__ out) {
    __shared__ float4 sA[NG];
    __shared__ float4 sB[NG];
    __shared__ unsigned long long sKey[NG];
    __shared__ int s_cnt;

    const int tid = threadIdx.x;
    const int bx  = blockIdx.x & 15;
    const int by  = blockIdx.x >> 4;
    const int x0  = bx * BLK_W;
    const int y0  = by * BLK_H;

    // parent 64x64 tile bounds (reference mask granularity)
    const float tu0 = (float)((x0 / TILE_SZ) * TILE_SZ);
    const float tv0 = (float)((y0 / TILE_SZ) * TILE_SZ);
    const float tu1 = tu0 + (float)TILE_SZ - 1.0f;
    const float tv1 = tv0 + (float)TILE_SZ - 1.0f;
    // padded sub-rect bounds
    const float su0 = (float)x0 - PAD;
    const float su1 = (float)(x0 + BLK_W - 1) + PAD;
    const float sv0 = (float)y0 - PAD;
    const float sv1 = (float)(y0 + BLK_H - 1) + PAD;

    if (tid == 0) s_cnt = 0;
    __syncthreads();

    // cull: 4 gaussians per thread, rect test only (1 LDG.128 each)
    int   own[4];
    unsigned long long ownK[4];
    int nOwn = 0;

    #pragma unroll
    for (int it = 0; it < NG / 256; it++) {
        int g = tid + it * 256;
        float4 R = g_R[g];
        bool mTile = (fminf(R.z, tu1) > fmaxf(R.x, tu0)) &&
                     (fminf(R.w, tv1) > fmaxf(R.y, tv0));
        bool mSub  = (fminf(R.z, su1) > fmaxf(R.x, su0)) &&
                     (fminf(R.w, sv1) > fmaxf(R.y, sv0));
        if (mTile && mSub) {
            unsigned long long k = g_key[g];
            int pos = atomicAdd(&s_cnt, 1);
            sKey[pos] = k;
            own[nOwn]  = g;
            ownK[nOwn] = k;
            nOwn++;
        }
    }
    __syncthreads();
    const int cnt = s_cnt;

    // depth-rank placement (keys unique -> perfect permutation)
    for (int o = 0; o < nOwn; o++) {
        unsigned long long k = ownK[o];
        int r = 0;
        for (int j = 0; j < cnt; j++) r += (sKey[j] < k) ? 1 : 0;
        int g = own[o];
        sA[r] = g_A[g];
        sB[r] = g_B[g];
    }
    __syncthreads();

    // composite: 1 px/thread, front-to-back
    int px = x0 + (tid & 15);
    int py = y0 + (tid >> 4);
    float fx = (float)px, fy = (float)py;

    float T = 1.0f, cr = 0.0f, cg = 0.0f, cb = 0.0f, dsum = 0.0f;

    for (int j0 = 0; j0 < cnt; j0 += 16) {
        int jend = min(j0 + 16, cnt);
        #pragma unroll 4
        for (int j = j0; j < jend; j++) {
            float4 A = sA[j];
            float dx = fx - A.x;
            float dy = fy - A.y;
            float d2 = fmaf(dx, dx, dy * dy);
            float e;
            asm("ex2.approx.ftz.f32 %0, %1;" : "=f"(e) : "f"(A.z * d2));
            float a = fminf(e * A.w, 0.99f);
            float w = a * T;
            float4 B = sB[j];
            cr   = fmaf(w, B.x, cr);
            cg   = fmaf(w, B.y, cg);
            cb   = fmaf(w, B.z, cb);
            dsum = fmaf(w, B.w, dsum);
            T    = T * (1.0f - a);
        }
        if (__all_sync(0xffffffffu, T <= 1e-6f)) break;
    }

    float acc = 1.0f - T;
    float bg  = T;
    int pix = py * IMG_W + px;
    out[pix*3 + 0] = fminf(fmaxf(cr + bg, 0.0f), 1.0f);
    out[pix*3 + 1] = fminf(fmaxf(cg + bg, 0.0f), 1.0f);
    out[pix*3 + 2] = fminf(fmaxf(cb + bg, 0.0f), 1.0f);
    out[IMG_W*IMG_H*3 + pix] = dsum;
    out[IMG_W*IMG_H*4 + pix] = acc;
}

extern "C" void kernel_launch(void* const* d_in, const int* in_sizes, int n_in,
                              void* d_out, int out_size) {
    const float* means3d  = (const float*)d_in[0];
    const float* opacity  = (const float*)d_in[1];
    const float* scale3d  = (const float*)d_in[2];
    const float* features = (const float*)d_in[3];
    const float* viewm    = (const float*)d_in[4];
    const float* projm    = (const float*)d_in[5];
    float* out = (float*)d_out;

    k_project<<<4, 256>>>(means3d, opacity, scale3d, features, viewm, projm);
    k_render<<<NBLK, 256>>>(out);
}